// round 15
// baseline (speedup 1.0000x reference)
#include <cuda_runtime.h>
#include <cuda_bf16.h>
#include <cstdint>

// ---------------------------------------------------------------------------
// GraphAttention: B=128, N=256, F=512, H=8, F_=64
// Output d_out: concat( output [128,256,512], dense4 [128,256,256] ) f32
// ---------------------------------------------------------------------------

__device__ float g_asn[524288];                // a_self [8][32768], a_neigh [8][32768]
__device__ float g_rowsum[128];
__device__ float g_s[128];
__device__ uint32_t g_amask[262144];           // [b][k=8][j=256] bit ii = A[b][k*32+ii][j]
__device__ __nv_bfloat16 g_Whi[262144];        // W^T hi: [n=512][f=512]
__device__ __nv_bfloat16 g_Wlo[262144];        // W^T lo
__device__ __nv_bfloat16 g_fhi[16777216];      // feats hi [32768][512]
__device__ __nv_bfloat16 g_flo[16777216];      // feats lo

__device__ __forceinline__ uint32_t smem_u32(const void* p) {
    uint32_t a;
    asm("{ .reg .u64 t; cvta.to.shared.u64 t, %1; cvt.u32.u64 %0, t; }" : "=r"(a) : "l"(p));
    return a;
}
__device__ __forceinline__ void mma16816(float* c, uint32_t a0, uint32_t a1,
                                         uint32_t a2, uint32_t a3,
                                         uint32_t b0, uint32_t b1) {
    asm volatile(
        "mma.sync.aligned.m16n8k16.row.col.f32.bf16.bf16.f32 "
        "{%0,%1,%2,%3}, {%4,%5,%6,%7}, {%8,%9}, {%0,%1,%2,%3};"
        : "+f"(c[0]), "+f"(c[1]), "+f"(c[2]), "+f"(c[3])
        : "r"(a0), "r"(a1), "r"(a2), "r"(a3), "r"(b0), "r"(b1));
}
__device__ __forceinline__ void ldsm_x4(uint32_t* r, uint32_t addr) {
    asm volatile("ldmatrix.sync.aligned.m8n8.x4.shared.b16 {%0,%1,%2,%3}, [%4];"
                 : "=r"(r[0]), "=r"(r[1]), "=r"(r[2]), "=r"(r[3]) : "r"(addr));
}
__device__ __forceinline__ void ldsm_x4_t(uint32_t* r, uint32_t addr) {
    asm volatile("ldmatrix.sync.aligned.m8n8.x4.trans.shared.b16 {%0,%1,%2,%3}, [%4];"
                 : "=r"(r[0]), "=r"(r[1]), "=r"(r[2]), "=r"(r[3]) : "r"(addr));
}
__device__ __forceinline__ void cp16(uint32_t dst, const void* src) {
    asm volatile("cp.async.cg.shared.global [%0], [%1], 16;" :: "r"(dst), "l"(src));
}
__device__ __forceinline__ void redadd(float* p, float v) {
    asm volatile("red.global.add.f32 [%0], %1;" :: "l"(p), "f"(v) : "memory");
}
#define CP_COMMIT() asm volatile("cp.async.commit_group;" ::: "memory")
#define CP_WAIT0()  asm volatile("cp.async.wait_group 0;" ::: "memory")

// split 8 fp32 -> 8 bf16 hi + 8 bf16 lo (packed uint4 each)
__device__ __forceinline__ void split8(const float* xp, uint4* hi, uint4* lo) {
    float4 x0 = *(const float4*)xp;
    float4 x1 = *(const float4*)(xp + 4);
    float xs[8] = {x0.x, x0.y, x0.z, x0.w, x1.x, x1.y, x1.z, x1.w};
    __nv_bfloat16 hb[8], lb[8];
#pragma unroll
    for (int i = 0; i < 8; ++i) {
        hb[i] = __float2bfloat16(xs[i]);
        lb[i] = __float2bfloat16(xs[i] - __bfloat162float(hb[i]));
    }
    *hi = *(uint4*)hb;
    *lo = *(uint4*)lb;
}

// ---------------------------------------------------------------------------
// K0: W^T split (blocks 0..1023) + alpha rowsums; zero view (1024..33791);
//     pack A bitmasks (33792..34815)
// ---------------------------------------------------------------------------
__global__ void prep_kernel(const float* __restrict__ kernels,
                            const float* __restrict__ alpha,
                            const float* __restrict__ Aadj,
                            float* __restrict__ view) {
    const int bid = blockIdx.x, t = threadIdx.x;
    if (bid < 1024) {
        int idx = bid * 256 + t;
        int n = idx >> 9, f = idx & 511;
        int h = n >> 6, kk = n & 63;
        float v = kernels[(h * 512 + f) * 64 + kk];
        __nv_bfloat16 hi = __float2bfloat16(v);
        g_Whi[idx] = hi;
        g_Wlo[idx] = __float2bfloat16(v - __bfloat162float(hi));
        if (idx < 128) {
            float s = 0.f;
            const float* ar = alpha + idx * 128;
#pragma unroll 4
            for (int k = 0; k < 128; ++k) s += ar[k];
            g_rowsum[idx] = s;
        }
    } else if (bid < 33792) {
        view[(size_t)(bid - 1024) * 256 + t] = 0.f;
    } else {
        int widx = (bid - 33792) * 256 + t;     // 0..262143
        int b = widx >> 11;
        int rem = widx & 2047;
        int k = rem >> 8, j = rem & 255;
        const float* ap = Aadj + ((size_t)b * 256 + k * 32) * 256 + j;
        uint32_t m = 0;
#pragma unroll
        for (int ii = 0; ii < 32; ++ii)
            m |= (ap[(size_t)ii * 256] > 0.5f) ? (1u << ii) : 0u;
        g_amask[widx] = m;
    }
}

// ---------------------------------------------------------------------------
// K1: feats = X @ W via mma.sync bf16 split (unchanged R14).
// ---------------------------------------------------------------------------
#define ROWB 80  // bytes per smem row (32 bf16 data + 8 pad)

__global__ __launch_bounds__(256, 2) void mma_gemm_kernel(
    const float* __restrict__ X,
    const float* __restrict__ attn_self, const float* __restrict__ attn_neigh) {
    __shared__ __align__(16) char sAhi[128 * ROWB];
    __shared__ __align__(16) char sAlo[128 * ROWB];
    __shared__ __align__(16) char sBhi[128 * ROWB];
    __shared__ __align__(16) char sBlo[128 * ROWB];
    __shared__ float s_self[512], s_neigh[512];

    const int t = threadIdx.x;
    const int lane = t & 31, warp = t >> 5;
    const int warp_m = warp & 3;
    const int warp_n = warp >> 2;
    const int lr = lane >> 2, lc = lane & 3;
    const int bm = blockIdx.y * 128;
    const int bn = blockIdx.x * 128;
    const uint32_t uAhi = smem_u32(sAhi), uAlo = smem_u32(sAlo);
    const uint32_t uBhi = smem_u32(sBhi), uBlo = smem_u32(sBlo);

    for (int u = t; u < 512; u += 256) { s_self[u] = attn_self[u]; s_neigh[u] = attn_neigh[u]; }

    float acc[2][8][4];
#pragma unroll
    for (int mi = 0; mi < 2; ++mi)
#pragma unroll
        for (int ni = 0; ni < 8; ++ni)
#pragma unroll
            for (int r = 0; r < 4; ++r) acc[mi][ni][r] = 0.f;

    const uint32_t a_lo = (uint32_t)((lane & 15) * ROWB + ((lane >> 4) << 4));
    const uint32_t b_lo = (uint32_t)((((lane >> 4) << 3) + (lane & 7)) * ROWB +
                                     (((lane >> 3) & 1) << 4));

    for (int c = 0; c < 16; ++c) {
        const int k0 = c * 32;
#pragma unroll
        for (int i = 0; i < 2; ++i) {
            int qq = t + 256 * i;
            int row = qq >> 2, c8 = qq & 3;
            uint32_t soff = row * ROWB + c8 * 16;
            size_t gb = (size_t)(bn + row) * 512 + k0 + c8 * 8;
            cp16(uBhi + soff, g_Whi + gb);
            cp16(uBlo + soff, g_Wlo + gb);
        }
        CP_COMMIT();
#pragma unroll
        for (int i = 0; i < 2; ++i) {
            int qq = t + 256 * i;
            int row = qq >> 2, c8 = qq & 3;
            uint32_t soff = row * ROWB + c8 * 16;
            uint4 hi, lo;
            split8(X + (size_t)(bm + row) * 512 + k0 + c8 * 8, &hi, &lo);
            *(uint4*)(sAhi + soff) = hi;
            *(uint4*)(sAlo + soff) = lo;
        }
        CP_WAIT0();
        __syncthreads();

#pragma unroll
        for (int ks = 0; ks < 2; ++ks) {
            uint32_t ahi[2][4], alo[2][4];
#pragma unroll
            for (int mi = 0; mi < 2; ++mi) {
                uint32_t ao = (uint32_t)((warp_m * 32 + mi * 16) * ROWB + ks * 32) + a_lo;
                ldsm_x4(ahi[mi], uAhi + ao);
                ldsm_x4(alo[mi], uAlo + ao);
            }
#pragma unroll
            for (int op = 0; op < 4; ++op) {
                uint32_t bo = (uint32_t)((warp_n * 64 + op * 16) * ROWB + ks * 32) + b_lo;
                uint32_t bh[4], bl[4];
                ldsm_x4(bh, uBhi + bo);
                ldsm_x4(bl, uBlo + bo);
#pragma unroll
                for (int hh = 0; hh < 2; ++hh) {
                    int ni = op * 2 + hh;
#pragma unroll
                    for (int mi = 0; mi < 2; ++mi) {
                        float* a = acc[mi][ni];
                        mma16816(a, ahi[mi][0], ahi[mi][1], ahi[mi][2], ahi[mi][3],
                                 bh[2 * hh], bh[2 * hh + 1]);
                        mma16816(a, ahi[mi][0], ahi[mi][1], ahi[mi][2], ahi[mi][3],
                                 bl[2 * hh], bl[2 * hh + 1]);
                        mma16816(a, alo[mi][0], alo[mi][1], alo[mi][2], alo[mi][3],
                                 bh[2 * hh], bh[2 * hh + 1]);
                    }
                }
            }
        }
        __syncthreads();
    }

    // ---- epilogue: feats hi/lo bf16 stores + inline a_self/a_neigh ----
    const int hh = (bn >> 6) + warp_n;
    float ps0[2] = {0.f, 0.f}, ps1[2] = {0.f, 0.f};
    float pn0[2] = {0.f, 0.f}, pn1[2] = {0.f, 0.f};
#pragma unroll
    for (int mi = 0; mi < 2; ++mi) {
        int row = bm + warp_m * 32 + mi * 16 + lr;
#pragma unroll
        for (int ni = 0; ni < 8; ++ni) {
            int col = bn + warp_n * 64 + ni * 8 + lc * 2;
            float v0 = acc[mi][ni][0], v1 = acc[mi][ni][1];
            float v2 = acc[mi][ni][2], v3 = acc[mi][ni][3];
            __nv_bfloat16 h0 = __float2bfloat16(v0), h1 = __float2bfloat16(v1);
            __nv_bfloat16 h2 = __float2bfloat16(v2), h3 = __float2bfloat16(v3);
            *(__nv_bfloat162*)(g_fhi + (size_t)row * 512 + col) = __nv_bfloat162(h0, h1);
            *(__nv_bfloat162*)(g_fhi + (size_t)(row + 8) * 512 + col) = __nv_bfloat162(h2, h3);
            *(__nv_bfloat162*)(g_flo + (size_t)row * 512 + col) = __nv_bfloat162(
                __float2bfloat16(v0 - __bfloat162float(h0)),
                __float2bfloat16(v1 - __bfloat162float(h1)));
            *(__nv_bfloat162*)(g_flo + (size_t)(row + 8) * 512 + col) = __nv_bfloat162(
                __float2bfloat16(v2 - __bfloat162float(h2)),
                __float2bfloat16(v3 - __bfloat162float(h3)));
            float s0 = s_self[col], s1 = s_self[col + 1];
            float q0 = s_neigh[col], q1 = s_neigh[col + 1];
            ps0[mi] += v0 * s0 + v1 * s1;
            ps1[mi] += v2 * s0 + v3 * s1;
            pn0[mi] += v0 * q0 + v1 * q1;
            pn1[mi] += v2 * q0 + v3 * q1;
        }
    }
#pragma unroll
    for (int mi = 0; mi < 2; ++mi) {
        float a0 = ps0[mi], a1 = ps1[mi], c0 = pn0[mi], c1 = pn1[mi];
        a0 += __shfl_xor_sync(0xffffffffu, a0, 1); a0 += __shfl_xor_sync(0xffffffffu, a0, 2);
        a1 += __shfl_xor_sync(0xffffffffu, a1, 1); a1 += __shfl_xor_sync(0xffffffffu, a1, 2);
        c0 += __shfl_xor_sync(0xffffffffu, c0, 1); c0 += __shfl_xor_sync(0xffffffffu, c0, 2);
        c1 += __shfl_xor_sync(0xffffffffu, c1, 1); c1 += __shfl_xor_sync(0xffffffffu, c1, 2);
        if (lc == 0) {
            int row = bm + warp_m * 32 + mi * 16 + lr;
            g_asn[hh * 32768 + row] = a0;
            g_asn[hh * 32768 + row + 8] = a1;
            g_asn[262144 + hh * 32768 + row] = c0;
            g_asn[262144 + hh * 32768 + row + 8] = c1;
        }
    }
}

// ---------------------------------------------------------------------------
// K3: fused attention v6: block = (head, batch). Feats filled ONCE per CTA;
// loop over 16 i-tiles; view via red.global.add (L2-resident).
// ---------------------------------------------------------------------------
#define AT_SFHI 0          // 32768: feats hi [256][64] bf16, XOR-swizzled
#define AT_SFLO 32768      // 32768: feats lo
#define AT_SWHI 65536      // 8448: w hi [16][264] bf16 (528B rows), unnormalized
#define AT_SWLO 73984      // 8448: w lo
#define AT_SSEL 82432      // 64
#define AT_SINV 82496      // 64
#define AT_SIZE 82560

__global__ __launch_bounds__(256, 2) void attn_kernel(
    const float* __restrict__ biases, float* __restrict__ out,
    float* __restrict__ view) {
    extern __shared__ char smc[];
    const uint32_t sbase = smem_u32(smc);
    float* ssel = (float*)(smc + AT_SSEL);
    float* sinv = (float*)(smc + AT_SINV);

    const int h = blockIdx.x;
    const int b = blockIdx.y;
    const int t = threadIdx.x;
    const int lane = t & 31, warp = t >> 5;
    const int gid = lane >> 2, tig = lane & 3;
    const uint32_t ONES = 0x3F803F80u;  // bf16 (1.0, 1.0)

    // --- feats hi/lo -> swizzled smem ONCE (cp.async) ---
#pragma unroll
    for (int i = 0; i < 8; ++i) {
        int q = t + 256 * i;           // 0..2047
        int j = q >> 3, c = q & 7;
        uint32_t so = (uint32_t)(j * 128 + ((c ^ (j & 7)) * 16));
        size_t g = (size_t)(b * 256 + j) * 512 + h * 64 + c * 8;
        cp16(sbase + AT_SFHI + so, g_fhi + g);
        cp16(sbase + AT_SFLO + so, g_flo + g);
    }
    CP_COMMIT();

    // --- per-thread constants (overlap with fill) ---
    uint32_t aw[8];
#pragma unroll
    for (int k = 0; k < 8; ++k) aw[k] = g_amask[b * 2048 + k * 256 + t];
    const float an = g_asn[262144 + h * 32768 + b * 256 + t];
    if (t < 16) ssel[t] = g_asn[h * 32768 + b * 256 + t];
    const int col = h * 64 + warp * 8 + tig * 2;
    const float bb0 = biases[col], bb1 = biases[col + 1];

    const uint32_t aw_lo = (uint32_t)((lane & 15) * 528 + ((lane >> 4) << 4));

    CP_WAIT0();
    __syncthreads();                                   // B0

    for (int it = 0; it < 16; ++it) {
        const int i0 = it * 16;
        const unsigned m = aw[it >> 1] >> ((it & 1) * 16);

        // --- logits + exp; store UNNORMALIZED w hi/lo ---
        float w[16];
#pragma unroll
        for (int i = 0; i < 16; ++i) {
            float z = ssel[i] + an;
            z = (z > 0.f) ? z : 0.2f * z;
            w[i] = ((m >> i) & 1u) ? __expf(z) : 0.f;
            __nv_bfloat16 wh = __float2bfloat16(w[i]);
            *(__nv_bfloat16*)(smc + AT_SWHI + i * 528 + t * 2) = wh;
            *(__nv_bfloat16*)(smc + AT_SWLO + i * 528 + t * 2) =
                __float2bfloat16(w[i] - __bfloat162float(wh));
        }
        __syncthreads();                               // B_b: w visible

        // --- mma: data (3) + ones rowsum (2) per kstep ---
        float acc[4] = {0.f, 0.f, 0.f, 0.f};
        float accR[4] = {0.f, 0.f, 0.f, 0.f};
#pragma unroll
        for (int ks = 0; ks < 16; ++ks) {
            const int k0 = ks * 16;
            uint32_t ah[4], al[4];
            uint32_t ao = aw_lo + (uint32_t)(k0 * 2);
            ldsm_x4(ah, sbase + AT_SWHI + ao);
            ldsm_x4(al, sbase + AT_SWLO + ao);
            int r = k0 + (lane & 15);
            uint32_t bb = (uint32_t)((lane < 16 ? AT_SFHI : AT_SFLO) +
                                     r * 128 + ((warp ^ (r & 7)) << 4));
            uint32_t bf[4];
            ldsm_x4_t(bf, sbase + bb);
            mma16816(acc, ah[0], ah[1], ah[2], ah[3], bf[0], bf[1]);
            mma16816(acc, ah[0], ah[1], ah[2], ah[3], bf[2], bf[3]);
            mma16816(acc, al[0], al[1], al[2], al[3], bf[0], bf[1]);
            mma16816(accR, ah[0], ah[1], ah[2], ah[3], ONES, ONES);
            mma16816(accR, al[0], al[1], al[2], al[3], ONES, ONES);
        }
        // --- normalize + bias + relu + store out; broadcast inv ---
        float inv0 = 1.f / accR[0];
        float inv1 = 1.f / accR[2];
        if (warp == 0 && tig == 0) { sinv[gid] = inv0; sinv[gid + 8] = inv1; }
        {
            float* o0 = out + (size_t)(b * 256 + i0 + gid) * 512 + col;
            *(float2*)o0 = make_float2(fmaxf(acc[0] * inv0 + bb0, 0.f),
                                       fmaxf(acc[1] * inv0 + bb1, 0.f));
            float* o1 = o0 + 8 * 512;
            *(float2*)o1 = make_float2(fmaxf(acc[2] * inv1 + bb0, 0.f),
                                       fmaxf(acc[3] * inv1 + bb1, 0.f));
        }
        if (t < 16 && it < 15)
            ssel[t] = g_asn[h * 32768 + b * 256 + i0 + 16 + t];
        __syncthreads();                               // B_c: sinv+ssel visible

        // --- view contribution via no-return global reduction ---
        float* vrow = view + (size_t)(b * 256 + i0) * 256 + t;
#pragma unroll
        for (int i = 0; i < 16; ++i)
            redadd(vrow + (size_t)i * 256, 0.125f * w[i] * sinv[i]);
    }
}

// ---------------------------------------------------------------------------
// K3b: pool: s[b] = sum( maxpool2x2(view[b]) * rowsum_alpha[pj] )
// ---------------------------------------------------------------------------
__global__ void pool_kernel(const float* __restrict__ view) {
    __shared__ float sp[8];
    const int b = blockIdx.x, t = threadIdx.x;
    const int pj = t & 127, ph = t >> 7;
    const float rs = g_rowsum[pj];
    const float* vb = view + (size_t)b * 65536;
    float part = 0.f;
#pragma unroll 4
    for (int k = 0; k < 64; ++k) {
        int pi = ph * 64 + k;
        const float* v0 = vb + (2 * pi) * 256 + 2 * pj;
        float2 a = *(const float2*)v0;
        float2 c = *(const float2*)(v0 + 256);
        part += fmaxf(fmaxf(a.x, a.y), fmaxf(c.x, c.y)) * rs;
    }
#pragma unroll
    for (int o = 16; o > 0; o >>= 1) part += __shfl_xor_sync(0xffffffffu, part, o);
    if ((t & 31) == 0) sp[t >> 5] = part;
    __syncthreads();
    if (t == 0) {
        float s = 0.f;
#pragma unroll
        for (int g = 0; g < 8; ++g) s += sp[g];
        g_s[b] = s;
    }
}

// ---------------------------------------------------------------------------
// K4: dense4 = (view + I < sigmoid(s[b])) ? 1 : 0, float4-vectorized
// ---------------------------------------------------------------------------
__global__ void binarize_kernel(float4* __restrict__ view4) {
    int idx = blockIdx.x * 256 + threadIdx.x;   // 2097152 float4s
    int b = idx >> 14;
    int rem = idx & 16383;
    int i = rem >> 6, j0 = (rem & 63) << 2;
    float th = 1.f / (1.f + expf(-g_s[b]));
    float4 v = view4[idx];
    v.x += (j0 == i) ? 1.f : 0.f;
    v.y += (j0 + 1 == i) ? 1.f : 0.f;
    v.z += (j0 + 2 == i) ? 1.f : 0.f;
    v.w += (j0 + 3 == i) ? 1.f : 0.f;
    v.x = (v.x < th) ? 1.f : 0.f;
    v.y = (v.y < th) ? 1.f : 0.f;
    v.z = (v.z < th) ? 1.f : 0.f;
    v.w = (v.w < th) ? 1.f : 0.f;
    view4[idx] = v;
}

// ---------------------------------------------------------------------------
extern "C" void kernel_launch(void* const* d_in, const int* in_sizes, int n_in,
                              void* d_out, int out_size) {
    const float* X          = (const float*)d_in[0];
    const float* Aadj       = (const float*)d_in[1];
    const float* kernels    = (const float*)d_in[2];
    const float* biases     = (const float*)d_in[3];
    const float* attn_self  = (const float*)d_in[4];
    const float* attn_neigh = (const float*)d_in[5];
    const float* alpha      = (const float*)d_in[6];
    float* out  = (float*)d_out;            // [128,256,512]
    float* view = out + 16777216;           // dense4 region [128,256,256]

    cudaFuncSetAttribute(attn_kernel, cudaFuncAttributeMaxDynamicSharedMemorySize, AT_SIZE);

    prep_kernel<<<34816, 256>>>(kernels, alpha, Aadj, view);
    mma_gemm_kernel<<<dim3(4, 256), 256>>>(X, attn_self, attn_neigh);
    attn_kernel<<<dim3(8, 128), 256, AT_SIZE>>>(biases, out, view);
    pool_kernel<<<128, 256>>>(view);
    binarize_kernel<<<8192, 256>>>((float4*)view);
}

// round 16
// speedup vs baseline: 1.2342x; 1.2342x over previous
#include <cuda_runtime.h>
#include <cuda_bf16.h>
#include <cstdint>

// ---------------------------------------------------------------------------
// GraphAttention: B=128, N=256, F=512, H=8, F_=64
// Output d_out: concat( output [128,256,512], dense4 [128,256,256] ) f32
// ---------------------------------------------------------------------------

__device__ float g_asn[524288];                // a_self [8][32768], a_neigh [8][32768]
__device__ float g_rowsum[128];
__device__ float g_s[128];
__device__ __nv_bfloat16 g_Whi[262144];        // W^T hi: [n=512][f=512]
__device__ __nv_bfloat16 g_Wlo[262144];        // W^T lo
__device__ __nv_bfloat16 g_fhi[16777216];      // feats hi [32768][512]
__device__ __nv_bfloat16 g_flo[16777216];      // feats lo

__device__ __forceinline__ uint32_t smem_u32(const void* p) {
    uint32_t a;
    asm("{ .reg .u64 t; cvta.to.shared.u64 t, %1; cvt.u32.u64 %0, t; }" : "=r"(a) : "l"(p));
    return a;
}
__device__ __forceinline__ void mma16816(float* c, uint32_t a0, uint32_t a1,
                                         uint32_t a2, uint32_t a3,
                                         uint32_t b0, uint32_t b1) {
    asm volatile(
        "mma.sync.aligned.m16n8k16.row.col.f32.bf16.bf16.f32 "
        "{%0,%1,%2,%3}, {%4,%5,%6,%7}, {%8,%9}, {%0,%1,%2,%3};"
        : "+f"(c[0]), "+f"(c[1]), "+f"(c[2]), "+f"(c[3])
        : "r"(a0), "r"(a1), "r"(a2), "r"(a3), "r"(b0), "r"(b1));
}
__device__ __forceinline__ void ldsm_x4(uint32_t* r, uint32_t addr) {
    asm volatile("ldmatrix.sync.aligned.m8n8.x4.shared.b16 {%0,%1,%2,%3}, [%4];"
                 : "=r"(r[0]), "=r"(r[1]), "=r"(r[2]), "=r"(r[3]) : "r"(addr));
}
__device__ __forceinline__ void ldsm_x4_t(uint32_t* r, uint32_t addr) {
    asm volatile("ldmatrix.sync.aligned.m8n8.x4.trans.shared.b16 {%0,%1,%2,%3}, [%4];"
                 : "=r"(r[0]), "=r"(r[1]), "=r"(r[2]), "=r"(r[3]) : "r"(addr));
}
__device__ __forceinline__ void cp16(uint32_t dst, const void* src) {
    asm volatile("cp.async.cg.shared.global [%0], [%1], 16;" :: "r"(dst), "l"(src));
}
#define CP_COMMIT() asm volatile("cp.async.commit_group;" ::: "memory")
#define CP_WAIT0()  asm volatile("cp.async.wait_group 0;" ::: "memory")
#define CP_WAIT1()  asm volatile("cp.async.wait_group 1;" ::: "memory")

// split 8 fp32 -> 8 bf16 hi + 8 bf16 lo (packed uint4 each)
__device__ __forceinline__ void split8(const float* xp, uint4* hi, uint4* lo) {
    float4 x0 = *(const float4*)xp;
    float4 x1 = *(const float4*)(xp + 4);
    float xs[8] = {x0.x, x0.y, x0.z, x0.w, x1.x, x1.y, x1.z, x1.w};
    __nv_bfloat16 hb[8], lb[8];
#pragma unroll
    for (int i = 0; i < 8; ++i) {
        hb[i] = __float2bfloat16(xs[i]);
        lb[i] = __float2bfloat16(xs[i] - __bfloat162float(hb[i]));
    }
    *hi = *(uint4*)hb;
    *lo = *(uint4*)lb;
}

// ---------------------------------------------------------------------------
// K0: W^T split to bf16 hi/lo, alpha row sums, zero g_s
// ---------------------------------------------------------------------------
__global__ void prep_kernel(const float* __restrict__ kernels,
                            const float* __restrict__ alpha) {
    int idx = blockIdx.x * 256 + threadIdx.x;
    if (idx < 262144) {
        int n = idx >> 9, f = idx & 511;
        int h = n >> 6, kk = n & 63;
        float v = kernels[(h * 512 + f) * 64 + kk];
        __nv_bfloat16 hi = __float2bfloat16(v);
        g_Whi[idx] = hi;
        g_Wlo[idx] = __float2bfloat16(v - __bfloat162float(hi));
    }
    if (idx < 128) {
        float s = 0.f;
        const float* ar = alpha + idx * 128;
#pragma unroll 4
        for (int k = 0; k < 128; ++k) s += ar[k];
        g_rowsum[idx] = s;
        g_s[idx] = 0.f;
    }
}

// ---------------------------------------------------------------------------
// K1: feats = X @ W via mma.sync bf16 split (unchanged R14).
// ---------------------------------------------------------------------------
#define ROWB 80  // bytes per smem row (32 bf16 data + 8 pad)

__global__ __launch_bounds__(256, 2) void mma_gemm_kernel(
    const float* __restrict__ X,
    const float* __restrict__ attn_self, const float* __restrict__ attn_neigh) {
    __shared__ __align__(16) char sAhi[128 * ROWB];
    __shared__ __align__(16) char sAlo[128 * ROWB];
    __shared__ __align__(16) char sBhi[128 * ROWB];
    __shared__ __align__(16) char sBlo[128 * ROWB];
    __shared__ float s_self[512], s_neigh[512];

    const int t = threadIdx.x;
    const int lane = t & 31, warp = t >> 5;
    const int warp_m = warp & 3;
    const int warp_n = warp >> 2;
    const int lr = lane >> 2, lc = lane & 3;
    const int bm = blockIdx.y * 128;
    const int bn = blockIdx.x * 128;
    const uint32_t uAhi = smem_u32(sAhi), uAlo = smem_u32(sAlo);
    const uint32_t uBhi = smem_u32(sBhi), uBlo = smem_u32(sBlo);

    for (int u = t; u < 512; u += 256) { s_self[u] = attn_self[u]; s_neigh[u] = attn_neigh[u]; }

    float acc[2][8][4];
#pragma unroll
    for (int mi = 0; mi < 2; ++mi)
#pragma unroll
        for (int ni = 0; ni < 8; ++ni)
#pragma unroll
            for (int r = 0; r < 4; ++r) acc[mi][ni][r] = 0.f;

    const uint32_t a_lo = (uint32_t)((lane & 15) * ROWB + ((lane >> 4) << 4));
    const uint32_t b_lo = (uint32_t)((((lane >> 4) << 3) + (lane & 7)) * ROWB +
                                     (((lane >> 3) & 1) << 4));

    for (int c = 0; c < 16; ++c) {
        const int k0 = c * 32;
#pragma unroll
        for (int i = 0; i < 2; ++i) {
            int qq = t + 256 * i;
            int row = qq >> 2, c8 = qq & 3;
            uint32_t soff = row * ROWB + c8 * 16;
            size_t gb = (size_t)(bn + row) * 512 + k0 + c8 * 8;
            cp16(uBhi + soff, g_Whi + gb);
            cp16(uBlo + soff, g_Wlo + gb);
        }
        CP_COMMIT();
#pragma unroll
        for (int i = 0; i < 2; ++i) {
            int qq = t + 256 * i;
            int row = qq >> 2, c8 = qq & 3;
            uint32_t soff = row * ROWB + c8 * 16;
            uint4 hi, lo;
            split8(X + (size_t)(bm + row) * 512 + k0 + c8 * 8, &hi, &lo);
            *(uint4*)(sAhi + soff) = hi;
            *(uint4*)(sAlo + soff) = lo;
        }
        CP_WAIT0();
        __syncthreads();

#pragma unroll
        for (int ks = 0; ks < 2; ++ks) {
            uint32_t ahi[2][4], alo[2][4];
#pragma unroll
            for (int mi = 0; mi < 2; ++mi) {
                uint32_t ao = (uint32_t)((warp_m * 32 + mi * 16) * ROWB + ks * 32) + a_lo;
                ldsm_x4(ahi[mi], uAhi + ao);
                ldsm_x4(alo[mi], uAlo + ao);
            }
#pragma unroll
            for (int op = 0; op < 4; ++op) {
                uint32_t bo = (uint32_t)((warp_n * 64 + op * 16) * ROWB + ks * 32) + b_lo;
                uint32_t bh[4], bl[4];
                ldsm_x4(bh, uBhi + bo);
                ldsm_x4(bl, uBlo + bo);
#pragma unroll
                for (int hh = 0; hh < 2; ++hh) {
                    int ni = op * 2 + hh;
#pragma unroll
                    for (int mi = 0; mi < 2; ++mi) {
                        float* a = acc[mi][ni];
                        mma16816(a, ahi[mi][0], ahi[mi][1], ahi[mi][2], ahi[mi][3],
                                 bh[2 * hh], bh[2 * hh + 1]);
                        mma16816(a, ahi[mi][0], ahi[mi][1], ahi[mi][2], ahi[mi][3],
                                 bl[2 * hh], bl[2 * hh + 1]);
                        mma16816(a, alo[mi][0], alo[mi][1], alo[mi][2], alo[mi][3],
                                 bh[2 * hh], bh[2 * hh + 1]);
                    }
                }
            }
        }
        __syncthreads();
    }

    // ---- epilogue: feats hi/lo bf16 stores + inline a_self/a_neigh ----
    const int hh = (bn >> 6) + warp_n;
    float ps0[2] = {0.f, 0.f}, ps1[2] = {0.f, 0.f};
    float pn0[2] = {0.f, 0.f}, pn1[2] = {0.f, 0.f};
#pragma unroll
    for (int mi = 0; mi < 2; ++mi) {
        int row = bm + warp_m * 32 + mi * 16 + lr;
#pragma unroll
        for (int ni = 0; ni < 8; ++ni) {
            int col = bn + warp_n * 64 + ni * 8 + lc * 2;
            float v0 = acc[mi][ni][0], v1 = acc[mi][ni][1];
            float v2 = acc[mi][ni][2], v3 = acc[mi][ni][3];
            __nv_bfloat16 h0 = __float2bfloat16(v0), h1 = __float2bfloat16(v1);
            __nv_bfloat16 h2 = __float2bfloat16(v2), h3 = __float2bfloat16(v3);
            *(__nv_bfloat162*)(g_fhi + (size_t)row * 512 + col) = __nv_bfloat162(h0, h1);
            *(__nv_bfloat162*)(g_fhi + (size_t)(row + 8) * 512 + col) = __nv_bfloat162(h2, h3);
            *(__nv_bfloat162*)(g_flo + (size_t)row * 512 + col) = __nv_bfloat162(
                __float2bfloat16(v0 - __bfloat162float(h0)),
                __float2bfloat16(v1 - __bfloat162float(h1)));
            *(__nv_bfloat162*)(g_flo + (size_t)(row + 8) * 512 + col) = __nv_bfloat162(
                __float2bfloat16(v2 - __bfloat162float(h2)),
                __float2bfloat16(v3 - __bfloat162float(h3)));
            float s0 = s_self[col], s1 = s_self[col + 1];
            float q0 = s_neigh[col], q1 = s_neigh[col + 1];
            ps0[mi] += v0 * s0 + v1 * s1;
            ps1[mi] += v2 * s0 + v3 * s1;
            pn0[mi] += v0 * q0 + v1 * q1;
            pn1[mi] += v2 * q0 + v3 * q1;
        }
    }
#pragma unroll
    for (int mi = 0; mi < 2; ++mi) {
        float a0 = ps0[mi], a1 = ps1[mi], c0 = pn0[mi], c1 = pn1[mi];
        a0 += __shfl_xor_sync(0xffffffffu, a0, 1); a0 += __shfl_xor_sync(0xffffffffu, a0, 2);
        a1 += __shfl_xor_sync(0xffffffffu, a1, 1); a1 += __shfl_xor_sync(0xffffffffu, a1, 2);
        c0 += __shfl_xor_sync(0xffffffffu, c0, 1); c0 += __shfl_xor_sync(0xffffffffu, c0, 2);
        c1 += __shfl_xor_sync(0xffffffffu, c1, 1); c1 += __shfl_xor_sync(0xffffffffu, c1, 2);
        if (lc == 0) {
            int row = bm + warp_m * 32 + mi * 16 + lr;
            g_asn[hh * 32768 + row] = a0;
            g_asn[hh * 32768 + row + 8] = a1;
            g_asn[262144 + hh * 32768 + row] = c0;
            g_asn[262144 + hh * 32768 + row + 8] = c1;
        }
    }
}

// ---------------------------------------------------------------------------
// K3: fused attention v7: R14 structure + correctly-scheduled cross-head
// fill pipeline. half0(h+1) hidden behind ks8-15+softmax; half1(h+1) behind
// vacc+softmax+next ks0-7. Waits split (wait_group 1 / 0), after softmax.
// ---------------------------------------------------------------------------
#define AT_SFHI 0          // 32768: feats hi [256][64] bf16, XOR-swizzled
#define AT_SFLO 32768      // 32768: feats lo
#define AT_SWHI 65536      // 8448: w hi [16][264] bf16 (528B rows), unnormalized
#define AT_SWLO 73984      // 8448: w lo
#define AT_SINV 82496      // 64
#define AT_SIZE 82560

__global__ __launch_bounds__(256, 2) void attn_kernel(
    const float* __restrict__ Aadj, const float* __restrict__ biases,
    float* __restrict__ out, float* __restrict__ view) {
    extern __shared__ char smc[];
    const uint32_t sbase = smem_u32(smc);
    float* sinv = (float*)(smc + AT_SINV);

    const int b = blockIdx.y;
    const int i0 = blockIdx.x * 16;
    const int t = threadIdx.x;
    const int lane = t & 31, warp = t >> 5;
    const int gid = lane >> 2, tig = lane & 3;
    const uint32_t ONES = 0x3F803F80u;  // bf16 (1.0, 1.0)

    // fill half of the feats tile for head h: rows [r0, r0+128)
    auto fill_half = [&](int h, int r0) {
#pragma unroll
        for (int i = 0; i < 4; ++i) {
            int q = t + 256 * i;           // 0..1023
            int j = r0 + (q >> 3), c = q & 7;
            uint32_t so = (uint32_t)(j * 128 + ((c ^ (j & 7)) * 16));
            size_t g = (size_t)(b * 256 + j) * 512 + h * 64 + c * 8;
            cp16(sbase + AT_SFHI + so, g_fhi + g);
            cp16(sbase + AT_SFLO + so, g_flo + g);
        }
    };

    // ---- prologue: start head-0 fill, overlap amask + softmax(0) ----
    fill_half(0, 0);
    fill_half(0, 128);
    CP_COMMIT();

    unsigned amask = 0u;
#pragma unroll
    for (int i = 0; i < 16; ++i)
        amask |= (Aadj[((size_t)b * 256 + i0 + i) * 256 + t] > 0.5f) ? (1u << i) : 0u;

    float w[16];
    // softmax for head h: logits+exp, store unnormalized w hi/lo to smem.
    // ssel via broadcast LDG (L1-hit), no smem stage.
    auto do_softmax = [&](int h) {
        float an = g_asn[262144 + h * 32768 + b * 256 + t];
        const float* sp = g_asn + h * 32768 + b * 256 + i0;
#pragma unroll
        for (int i = 0; i < 16; ++i) {
            float z = __ldg(sp + i) + an;
            z = (z > 0.f) ? z : 0.2f * z;
            w[i] = ((amask >> i) & 1u) ? __expf(z) : 0.f;
            __nv_bfloat16 wh = __float2bfloat16(w[i]);
            *(__nv_bfloat16*)(smc + AT_SWHI + i * 528 + t * 2) = wh;
            *(__nv_bfloat16*)(smc + AT_SWLO + i * 528 + t * 2) =
                __float2bfloat16(w[i] - __bfloat162float(wh));
        }
    };

    float vacc[16];
#pragma unroll
    for (int i = 0; i < 16; ++i) vacc[i] = 0.f;

    const uint32_t aw_lo = (uint32_t)((lane & 15) * 528 + ((lane >> 4) << 4));

    do_softmax(0);
    CP_WAIT0();
    __syncthreads();                               // feats(0) + w(0) visible

    for (int h = 0; h < 8; ++h) {
        float acc[4] = {0.f, 0.f, 0.f, 0.f};
        float accR[4] = {0.f, 0.f, 0.f, 0.f};
        // --- mma k-steps 0..7 (feat rows 0..127) ---
#pragma unroll
        for (int ks = 0; ks < 8; ++ks) {
            const int k0 = ks * 16;
            uint32_t ah[4], al[4];
            uint32_t ao = aw_lo + (uint32_t)(k0 * 2);
            ldsm_x4(ah, sbase + AT_SWHI + ao);
            ldsm_x4(al, sbase + AT_SWLO + ao);
            int r = k0 + (lane & 15);
            uint32_t bb = (uint32_t)((lane < 16 ? AT_SFHI : AT_SFLO) +
                                     r * 128 + ((warp ^ (r & 7)) << 4));
            uint32_t bf[4];
            ldsm_x4_t(bf, sbase + bb);
            mma16816(acc, ah[0], ah[1], ah[2], ah[3], bf[0], bf[1]);
            mma16816(acc, ah[0], ah[1], ah[2], ah[3], bf[2], bf[3]);
            mma16816(acc, al[0], al[1], al[2], al[3], bf[0], bf[1]);
            mma16816(accR, ah[0], ah[1], ah[2], ah[3], ONES, ONES);
            mma16816(accR, al[0], al[1], al[2], al[3], ONES, ONES);
        }
        __syncthreads();                           // S1: half0(h) reads done
        if (h < 7) {
            fill_half(h + 1, 0);                   // overwrites rows 0..127
            CP_COMMIT();
            CP_WAIT1();                            // ensure fill1(h) landed
        } else {
            CP_WAIT0();
        }
        __syncthreads();                           // S2: half1(h) visible
        // --- mma k-steps 8..15 (feat rows 128..255) ---
#pragma unroll
        for (int ks = 8; ks < 16; ++ks) {
            const int k0 = ks * 16;
            uint32_t ah[4], al[4];
            uint32_t ao = aw_lo + (uint32_t)(k0 * 2);
            ldsm_x4(ah, sbase + AT_SWHI + ao);
            ldsm_x4(al, sbase + AT_SWLO + ao);
            int r = k0 + (lane & 15);
            uint32_t bb = (uint32_t)((lane < 16 ? AT_SFHI : AT_SFLO) +
                                     r * 128 + ((warp ^ (r & 7)) << 4));
            uint32_t bf[4];
            ldsm_x4_t(bf, sbase + bb);
            mma16816(acc, ah[0], ah[1], ah[2], ah[3], bf[0], bf[1]);
            mma16816(acc, ah[0], ah[1], ah[2], ah[3], bf[2], bf[3]);
            mma16816(acc, al[0], al[1], al[2], al[3], bf[0], bf[1]);
            mma16816(accR, ah[0], ah[1], ah[2], ah[3], ONES, ONES);
            mma16816(accR, al[0], al[1], al[2], al[3], ONES, ONES);
        }
        // --- normalize + bias + relu + store out; broadcast inv ---
        float inv0 = 1.f / accR[0];
        float inv1 = 1.f / accR[2];
        if (warp == 0 && tig == 0) { sinv[gid] = inv0; sinv[gid + 8] = inv1; }
        {
            int col = h * 64 + warp * 8 + tig * 2;
            float b0 = biases[col], b1 = biases[col + 1];
            float* o0 = out + (size_t)(b * 256 + i0 + gid) * 512 + col;
            *(float2*)o0 = make_float2(fmaxf(acc[0] * inv0 + b0, 0.f),
                                       fmaxf(acc[1] * inv0 + b1, 0.f));
            float* o1 = o0 + 8 * 512;
            *(float2*)o1 = make_float2(fmaxf(acc[2] * inv1 + b0, 0.f),
                                       fmaxf(acc[3] * inv1 + b1, 0.f));
        }
        __syncthreads();                           // S3: half1(h)+w(h) reads done, sinv visible
        if (h < 7) {
            fill_half(h + 1, 128);                 // overwrites rows 128..255
            CP_COMMIT();
        }
        // --- view accumulation with full-precision register w(h) ---
#pragma unroll
        for (int i = 0; i < 16; ++i)
            vacc[i] += 0.125f * w[i] * sinv[i];
        if (h < 7) {
            do_softmax(h + 1);                     // w readers drained at S3
            CP_WAIT1();                            // ensure fill0(h+1) landed
            __syncthreads();                       // S4: half0(h+1)+w(h+1) visible
        }
    }

    // --- view store ---
#pragma unroll
    for (int i = 0; i < 16; ++i)
        view[((size_t)b * 256 + i0 + i) * 256 + t] = vacc[i];

    // --- 2x2 max pool + s[b] partial ---
    float part = 0.f;
    float rs = g_rowsum[t >> 1];
#pragma unroll
    for (int pi = 0; pi < 8; ++pi) {
        float rm = fmaxf(vacc[2 * pi], vacc[2 * pi + 1]);
        rm = fmaxf(rm, __shfl_xor_sync(0xffffffffu, rm, 1));
        if (!(t & 1)) part += rm * rs;
    }
#pragma unroll
    for (int o = 16; o > 0; o >>= 1) part += __shfl_xor_sync(0xffffffffu, part, o);
    if (lane == 0) atomicAdd(&g_s[b], part);
}

// ---------------------------------------------------------------------------
// K4: dense4 = (view + I < sigmoid(s[b])) ? 1 : 0, float4-vectorized
// ---------------------------------------------------------------------------
__global__ void binarize_kernel(float4* __restrict__ view4) {
    int idx = blockIdx.x * 256 + threadIdx.x;   // 2097152 float4s
    int b = idx >> 14;
    int rem = idx & 16383;
    int i = rem >> 6, j0 = (rem & 63) << 2;
    float th = 1.f / (1.f + expf(-g_s[b]));
    float4 v = view4[idx];
    v.x += (j0 == i) ? 1.f : 0.f;
    v.y += (j0 + 1 == i) ? 1.f : 0.f;
    v.z += (j0 + 2 == i) ? 1.f : 0.f;
    v.w += (j0 + 3 == i) ? 1.f : 0.f;
    v.x = (v.x < th) ? 1.f : 0.f;
    v.y = (v.y < th) ? 1.f : 0.f;
    v.z = (v.z < th) ? 1.f : 0.f;
    v.w = (v.w < th) ? 1.f : 0.f;
    view4[idx] = v;
}

// ---------------------------------------------------------------------------
extern "C" void kernel_launch(void* const* d_in, const int* in_sizes, int n_in,
                              void* d_out, int out_size) {
    const float* X          = (const float*)d_in[0];
    const float* Aadj       = (const float*)d_in[1];
    const float* kernels    = (const float*)d_in[2];
    const float* biases     = (const float*)d_in[3];
    const float* attn_self  = (const float*)d_in[4];
    const float* attn_neigh = (const float*)d_in[5];
    const float* alpha      = (const float*)d_in[6];
    float* out  = (float*)d_out;            // [128,256,512]
    float* view = out + 16777216;           // dense4 region [128,256,256]

    cudaFuncSetAttribute(attn_kernel, cudaFuncAttributeMaxDynamicSharedMemorySize, AT_SIZE);

    prep_kernel<<<1024, 256>>>(kernels, alpha);
    mma_gemm_kernel<<<dim3(4, 256), 256>>>(X, attn_self, attn_neigh);
    attn_kernel<<<dim3(16, 128), 256, AT_SIZE>>>(Aadj, biases, out, view);
    binarize_kernel<<<8192, 256>>>((float4*)view);
}

// round 17
// speedup vs baseline: 1.2711x; 1.0299x over previous
#include <cuda_runtime.h>
#include <cuda_bf16.h>
#include <cstdint>

// ---------------------------------------------------------------------------
// GraphAttention: B=128, N=256, F=512, H=8, F_=64
// Output d_out: concat( output [128,256,512], dense4 [128,256,256] ) f32
// ---------------------------------------------------------------------------

__device__ float g_asn[524288];                // a_self [8][32768], a_neigh [8][32768]
__device__ float g_rowsum[128];
__device__ float g_s[128];
__device__ __nv_bfloat16 g_Whi[262144];        // W^T hi: [n=512][f=512]
__device__ __nv_bfloat16 g_Wlo[262144];        // W^T lo
__device__ __nv_bfloat16 g_fhi[16777216];      // feats hi [32768][512]
__device__ __nv_bfloat16 g_flo[16777216];      // feats lo

__device__ __forceinline__ uint32_t smem_u32(const void* p) {
    uint32_t a;
    asm("{ .reg .u64 t; cvta.to.shared.u64 t, %1; cvt.u32.u64 %0, t; }" : "=r"(a) : "l"(p));
    return a;
}
__device__ __forceinline__ void mma16816(float* c, uint32_t a0, uint32_t a1,
                                         uint32_t a2, uint32_t a3,
                                         uint32_t b0, uint32_t b1) {
    asm volatile(
        "mma.sync.aligned.m16n8k16.row.col.f32.bf16.bf16.f32 "
        "{%0,%1,%2,%3}, {%4,%5,%6,%7}, {%8,%9}, {%0,%1,%2,%3};"
        : "+f"(c[0]), "+f"(c[1]), "+f"(c[2]), "+f"(c[3])
        : "r"(a0), "r"(a1), "r"(a2), "r"(a3), "r"(b0), "r"(b1));
}
__device__ __forceinline__ void ldsm_x4(uint32_t* r, uint32_t addr) {
    asm volatile("ldmatrix.sync.aligned.m8n8.x4.shared.b16 {%0,%1,%2,%3}, [%4];"
                 : "=r"(r[0]), "=r"(r[1]), "=r"(r[2]), "=r"(r[3]) : "r"(addr));
}
__device__ __forceinline__ void ldsm_x4_t(uint32_t* r, uint32_t addr) {
    asm volatile("ldmatrix.sync.aligned.m8n8.x4.trans.shared.b16 {%0,%1,%2,%3}, [%4];"
                 : "=r"(r[0]), "=r"(r[1]), "=r"(r[2]), "=r"(r[3]) : "r"(addr));
}
__device__ __forceinline__ void cp16(uint32_t dst, const void* src) {
    asm volatile("cp.async.cg.shared.global [%0], [%1], 16;" :: "r"(dst), "l"(src));
}
#define CP_COMMIT() asm volatile("cp.async.commit_group;" ::: "memory")
#define CP_WAIT0()  asm volatile("cp.async.wait_group 0;" ::: "memory")
#define CP_WAIT1()  asm volatile("cp.async.wait_group 1;" ::: "memory")

// ---------------------------------------------------------------------------
// K0: W^T split to bf16 hi/lo, alpha row sums, zero g_s
// ---------------------------------------------------------------------------
__global__ void prep_kernel(const float* __restrict__ kernels,
                            const float* __restrict__ alpha) {
    int idx = blockIdx.x * 256 + threadIdx.x;
    if (idx < 262144) {
        int n = idx >> 9, f = idx & 511;
        int h = n >> 6, kk = n & 63;
        float v = kernels[(h * 512 + f) * 64 + kk];
        __nv_bfloat16 hi = __float2bfloat16(v);
        g_Whi[idx] = hi;
        g_Wlo[idx] = __float2bfloat16(v - __bfloat162float(hi));
    }
    if (idx < 128) {
        float s = 0.f;
        const float* ar = alpha + idx * 128;
#pragma unroll 4
        for (int k = 0; k < 128; ++k) s += ar[k];
        g_rowsum[idx] = s;
        g_s[idx] = 0.f;
    }
}

// ---------------------------------------------------------------------------
// K1: feats = X @ W via mma.sync bf16 split, software-pipelined:
// double-buffered smem (2 x 40KB dynamic), cp.async B(c+1) + X(c+1)-in-regs
// issued BEFORE mma(c); one barrier per chunk.
// ---------------------------------------------------------------------------
#define ROWB 80  // bytes per smem row (32 bf16 data + 8 pad)
#define GB_A_HI 0
#define GB_A_LO 10240
#define GB_B_HI 20480
#define GB_B_LO 30720
#define GB_STRIDE 40960
#define GB_SMEM 81920

__global__ __launch_bounds__(256, 2) void mma_gemm_kernel(
    const float* __restrict__ X,
    const float* __restrict__ attn_self, const float* __restrict__ attn_neigh) {
    extern __shared__ char sdyn[];
    __shared__ float s_self[512], s_neigh[512];
    const uint32_t sb = smem_u32(sdyn);

    const int t = threadIdx.x;
    const int lane = t & 31, warp = t >> 5;
    const int warp_m = warp & 3;
    const int warp_n = warp >> 2;
    const int lr = lane >> 2, lc = lane & 3;
    const int bm = blockIdx.y * 128;
    const int bn = blockIdx.x * 128;

    for (int u = t; u < 512; u += 256) { s_self[u] = attn_self[u]; s_neigh[u] = attn_neigh[u]; }

    float acc[2][8][4];
#pragma unroll
    for (int mi = 0; mi < 2; ++mi)
#pragma unroll
        for (int ni = 0; ni < 8; ++ni)
#pragma unroll
            for (int r = 0; r < 4; ++r) acc[mi][ni][r] = 0.f;

    const uint32_t a_lo = (uint32_t)((lane & 15) * ROWB + ((lane >> 4) << 4));
    const uint32_t b_lo = (uint32_t)((((lane >> 4) << 3) + (lane & 7)) * ROWB +
                                     (((lane >> 3) & 1) << 4));
    // per-thread fill coords (2 positions: q = t, t+256)
    const int row0 = t >> 2, c80 = t & 3;
    const int row1 = (t + 256) >> 2, c81 = t & 3;
    const uint32_t soff0 = (uint32_t)(row0 * ROWB + c80 * 16);
    const uint32_t soff1 = (uint32_t)(row1 * ROWB + c81 * 16);

    float4 xq[4];  // X prefetch registers (2 positions x 8 floats)
    auto ldgX = [&](int c) {
        const float* p0 = X + (size_t)(bm + row0) * 512 + c * 32 + c80 * 8;
        const float* p1 = X + (size_t)(bm + row1) * 512 + c * 32 + c81 * 8;
        xq[0] = *(const float4*)p0;
        xq[1] = *(const float4*)(p0 + 4);
        xq[2] = *(const float4*)p1;
        xq[3] = *(const float4*)(p1 + 4);
    };
    auto cpB = [&](int c, int sel) {
        uint32_t base = sb + sel * GB_STRIDE;
        size_t gb0 = (size_t)(bn + row0) * 512 + c * 32 + c80 * 8;
        size_t gb1 = (size_t)(bn + row1) * 512 + c * 32 + c81 * 8;
        cp16(base + GB_B_HI + soff0, g_Whi + gb0);
        cp16(base + GB_B_LO + soff0, g_Wlo + gb0);
        cp16(base + GB_B_HI + soff1, g_Whi + gb1);
        cp16(base + GB_B_LO + soff1, g_Wlo + gb1);
    };
    auto stsA = [&](int sel) {
        char* base = sdyn + sel * GB_STRIDE;
#pragma unroll
        for (int i = 0; i < 2; ++i) {
            float xs[8];
            *(float4*)(xs)     = xq[2 * i];
            *(float4*)(xs + 4) = xq[2 * i + 1];
            __nv_bfloat16 hb[8], lb[8];
#pragma unroll
            for (int k = 0; k < 8; ++k) {
                hb[k] = __float2bfloat16(xs[k]);
                lb[k] = __float2bfloat16(xs[k] - __bfloat162float(hb[k]));
            }
            uint32_t so = (i == 0) ? soff0 : soff1;
            *(uint4*)(base + GB_A_HI + so) = *(uint4*)hb;
            *(uint4*)(base + GB_A_LO + so) = *(uint4*)lb;
        }
    };

    cpB(0, 0);
    CP_COMMIT();
    ldgX(0);

    for (int c = 0; c < 16; ++c) {
        const int sel = c & 1;
        stsA(sel);                    // consume xq(c)
        CP_WAIT0();                   // B(c) landed
        __syncthreads();              // A(c)+B(c) visible; prior mma done
        if (c < 15) {
            cpB(c + 1, sel ^ 1);      // lands during mma(c)
            CP_COMMIT();
            ldgX(c + 1);              // lands during mma(c)
        }

        const uint32_t uAhi = sb + sel * GB_STRIDE + GB_A_HI;
        const uint32_t uAlo = sb + sel * GB_STRIDE + GB_A_LO;
        const uint32_t uBhi = sb + sel * GB_STRIDE + GB_B_HI;
        const uint32_t uBlo = sb + sel * GB_STRIDE + GB_B_LO;
#pragma unroll
        for (int ks = 0; ks < 2; ++ks) {
            uint32_t ahi[2][4], alo[2][4];
#pragma unroll
            for (int mi = 0; mi < 2; ++mi) {
                uint32_t ao = (uint32_t)((warp_m * 32 + mi * 16) * ROWB + ks * 32) + a_lo;
                ldsm_x4(ahi[mi], uAhi + ao);
                ldsm_x4(alo[mi], uAlo + ao);
            }
#pragma unroll
            for (int op = 0; op < 4; ++op) {
                uint32_t bo = (uint32_t)((warp_n * 64 + op * 16) * ROWB + ks * 32) + b_lo;
                uint32_t bh[4], bl[4];
                ldsm_x4(bh, uBhi + bo);
                ldsm_x4(bl, uBlo + bo);
#pragma unroll
                for (int hh = 0; hh < 2; ++hh) {
                    int ni = op * 2 + hh;
#pragma unroll
                    for (int mi = 0; mi < 2; ++mi) {
                        float* a = acc[mi][ni];
                        mma16816(a, ahi[mi][0], ahi[mi][1], ahi[mi][2], ahi[mi][3],
                                 bh[2 * hh], bh[2 * hh + 1]);
                        mma16816(a, ahi[mi][0], ahi[mi][1], ahi[mi][2], ahi[mi][3],
                                 bl[2 * hh], bl[2 * hh + 1]);
                        mma16816(a, alo[mi][0], alo[mi][1], alo[mi][2], alo[mi][3],
                                 bh[2 * hh], bh[2 * hh + 1]);
                    }
                }
            }
        }
        // no post-mma barrier needed: next iteration's top barrier (after
        // stsA into buf sel^1, which nobody is reading) orders everything.
    }
    __syncthreads();

    // ---- epilogue: feats hi/lo bf16 stores + inline a_self/a_neigh ----
    const int hh = (bn >> 6) + warp_n;
    float ps0[2] = {0.f, 0.f}, ps1[2] = {0.f, 0.f};
    float pn0[2] = {0.f, 0.f}, pn1[2] = {0.f, 0.f};
#pragma unroll
    for (int mi = 0; mi < 2; ++mi) {
        int row = bm + warp_m * 32 + mi * 16 + lr;
#pragma unroll
        for (int ni = 0; ni < 8; ++ni) {
            int col = bn + warp_n * 64 + ni * 8 + lc * 2;
            float v0 = acc[mi][ni][0], v1 = acc[mi][ni][1];
            float v2 = acc[mi][ni][2], v3 = acc[mi][ni][3];
            __nv_bfloat16 h0 = __float2bfloat16(v0), h1 = __float2bfloat16(v1);
            __nv_bfloat16 h2 = __float2bfloat16(v2), h3 = __float2bfloat16(v3);
            *(__nv_bfloat162*)(g_fhi + (size_t)row * 512 + col) = __nv_bfloat162(h0, h1);
            *(__nv_bfloat162*)(g_fhi + (size_t)(row + 8) * 512 + col) = __nv_bfloat162(h2, h3);
            *(__nv_bfloat162*)(g_flo + (size_t)row * 512 + col) = __nv_bfloat162(
                __float2bfloat16(v0 - __bfloat162float(h0)),
                __float2bfloat16(v1 - __bfloat162float(h1)));
            *(__nv_bfloat162*)(g_flo + (size_t)(row + 8) * 512 + col) = __nv_bfloat162(
                __float2bfloat16(v2 - __bfloat162float(h2)),
                __float2bfloat16(v3 - __bfloat162float(h3)));
            float s0 = s_self[col], s1 = s_self[col + 1];
            float q0 = s_neigh[col], q1 = s_neigh[col + 1];
            ps0[mi] += v0 * s0 + v1 * s1;
            ps1[mi] += v2 * s0 + v3 * s1;
            pn0[mi] += v0 * q0 + v1 * q1;
            pn1[mi] += v2 * q0 + v3 * q1;
        }
    }
#pragma unroll
    for (int mi = 0; mi < 2; ++mi) {
        float a0 = ps0[mi], a1 = ps1[mi], c0 = pn0[mi], c1 = pn1[mi];
        a0 += __shfl_xor_sync(0xffffffffu, a0, 1); a0 += __shfl_xor_sync(0xffffffffu, a0, 2);
        a1 += __shfl_xor_sync(0xffffffffu, a1, 1); a1 += __shfl_xor_sync(0xffffffffu, a1, 2);
        c0 += __shfl_xor_sync(0xffffffffu, c0, 1); c0 += __shfl_xor_sync(0xffffffffu, c0, 2);
        c1 += __shfl_xor_sync(0xffffffffu, c1, 1); c1 += __shfl_xor_sync(0xffffffffu, c1, 2);
        if (lc == 0) {
            int row = bm + warp_m * 32 + mi * 16 + lr;
            g_asn[hh * 32768 + row] = a0;
            g_asn[hh * 32768 + row + 8] = a1;
            g_asn[262144 + hh * 32768 + row] = c0;
            g_asn[262144 + hh * 32768 + row + 8] = c1;
        }
    }
}

// ---------------------------------------------------------------------------
// K3: fused attention v7 (R16 winner, unchanged): cross-head pipelined fills.
// ---------------------------------------------------------------------------
#define AT_SFHI 0          // 32768: feats hi [256][64] bf16, XOR-swizzled
#define AT_SFLO 32768      // 32768: feats lo
#define AT_SWHI 65536      // 8448: w hi [16][264] bf16 (528B rows), unnormalized
#define AT_SWLO 73984      // 8448: w lo
#define AT_SINV 82496      // 64
#define AT_SIZE 82560

__global__ __launch_bounds__(256, 2) void attn_kernel(
    const float* __restrict__ Aadj, const float* __restrict__ biases,
    float* __restrict__ out, float* __restrict__ view) {
    extern __shared__ char smc[];
    const uint32_t sbase = smem_u32(smc);
    float* sinv = (float*)(smc + AT_SINV);

    const int b = blockIdx.y;
    const int i0 = blockIdx.x * 16;
    const int t = threadIdx.x;
    const int lane = t & 31, warp = t >> 5;
    const int gid = lane >> 2, tig = lane & 3;
    const uint32_t ONES = 0x3F803F80u;  // bf16 (1.0, 1.0)

    auto fill_half = [&](int h, int r0) {
#pragma unroll
        for (int i = 0; i < 4; ++i) {
            int q = t + 256 * i;           // 0..1023
            int j = r0 + (q >> 3), c = q & 7;
            uint32_t so = (uint32_t)(j * 128 + ((c ^ (j & 7)) * 16));
            size_t g = (size_t)(b * 256 + j) * 512 + h * 64 + c * 8;
            cp16(sbase + AT_SFHI + so, g_fhi + g);
            cp16(sbase + AT_SFLO + so, g_flo + g);
        }
    };

    fill_half(0, 0);
    fill_half(0, 128);
    CP_COMMIT();

    unsigned amask = 0u;
#pragma unroll
    for (int i = 0; i < 16; ++i)
        amask |= (Aadj[((size_t)b * 256 + i0 + i) * 256 + t] > 0.5f) ? (1u << i) : 0u;

    float w[16];
    auto do_softmax = [&](int h) {
        float an = g_asn[262144 + h * 32768 + b * 256 + t];
        const float* sp = g_asn + h * 32768 + b * 256 + i0;
#pragma unroll
        for (int i = 0; i < 16; ++i) {
            float z = __ldg(sp + i) + an;
            z = (z > 0.f) ? z : 0.2f * z;
            w[i] = ((amask >> i) & 1u) ? __expf(z) : 0.f;
            __nv_bfloat16 wh = __float2bfloat16(w[i]);
            *(__nv_bfloat16*)(smc + AT_SWHI + i * 528 + t * 2) = wh;
            *(__nv_bfloat16*)(smc + AT_SWLO + i * 528 + t * 2) =
                __float2bfloat16(w[i] - __bfloat162float(wh));
        }
    };

    float vacc[16];
#pragma unroll
    for (int i = 0; i < 16; ++i) vacc[i] = 0.f;

    const uint32_t aw_lo = (uint32_t)((lane & 15) * 528 + ((lane >> 4) << 4));

    do_softmax(0);
    CP_WAIT0();
    __syncthreads();                               // feats(0) + w(0) visible

    for (int h = 0; h < 8; ++h) {
        float acc[4] = {0.f, 0.f, 0.f, 0.f};
        float accR[4] = {0.f, 0.f, 0.f, 0.f};
#pragma unroll
        for (int ks = 0; ks < 8; ++ks) {
            const int k0 = ks * 16;
            uint32_t ah[4], al[4];
            uint32_t ao = aw_lo + (uint32_t)(k0 * 2);
            ldsm_x4(ah, sbase + AT_SWHI + ao);
            ldsm_x4(al, sbase + AT_SWLO + ao);
            int r = k0 + (lane & 15);
            uint32_t bb = (uint32_t)((lane < 16 ? AT_SFHI : AT_SFLO) +
                                     r * 128 + ((warp ^ (r & 7)) << 4));
            uint32_t bf[4];
            ldsm_x4_t(bf, sbase + bb);
            mma16816(acc, ah[0], ah[1], ah[2], ah[3], bf[0], bf[1]);
            mma16816(acc, ah[0], ah[1], ah[2], ah[3], bf[2], bf[3]);
            mma16816(acc, al[0], al[1], al[2], al[3], bf[0], bf[1]);
            mma16816(accR, ah[0], ah[1], ah[2], ah[3], ONES, ONES);
            mma16816(accR, al[0], al[1], al[2], al[3], ONES, ONES);
        }
        __syncthreads();                           // S1: half0(h) reads done
        if (h < 7) {
            fill_half(h + 1, 0);
            CP_COMMIT();
            CP_WAIT1();                            // ensure fill1(h) landed
        } else {
            CP_WAIT0();
        }
        __syncthreads();                           // S2: half1(h) visible
#pragma unroll
        for (int ks = 8; ks < 16; ++ks) {
            const int k0 = ks * 16;
            uint32_t ah[4], al[4];
            uint32_t ao = aw_lo + (uint32_t)(k0 * 2);
            ldsm_x4(ah, sbase + AT_SWHI + ao);
            ldsm_x4(al, sbase + AT_SWLO + ao);
            int r = k0 + (lane & 15);
            uint32_t bb = (uint32_t)((lane < 16 ? AT_SFHI : AT_SFLO) +
                                     r * 128 + ((warp ^ (r & 7)) << 4));
            uint32_t bf[4];
            ldsm_x4_t(bf, sbase + bb);
            mma16816(acc, ah[0], ah[1], ah[2], ah[3], bf[0], bf[1]);
            mma16816(acc, ah[0], ah[1], ah[2], ah[3], bf[2], bf[3]);
            mma16816(acc, al[0], al[1], al[2], al[3], bf[0], bf[1]);
            mma16816(accR, ah[0], ah[1], ah[2], ah[3], ONES, ONES);
            mma16816(accR, al[0], al[1], al[2], al[3], ONES, ONES);
        }
        float inv0 = 1.f / accR[0];
        float inv1 = 1.f / accR[2];
        if (warp == 0 && tig == 0) { sinv[gid] = inv0; sinv[gid + 8] = inv1; }
        {
            int col = h * 64 + warp * 8 + tig * 2;
            float b0 = biases[col], b1 = biases[col + 1];
            float* o0 = out + (size_t)(b * 256 + i0 + gid) * 512 + col;
            *(float2*)o0 = make_float2(fmaxf(acc[0] * inv0 + b0, 0.f),
                                       fmaxf(acc[1] * inv0 + b1, 0.f));
            float* o1 = o0 + 8 * 512;
            *(float2*)o1 = make_float2(fmaxf(acc[2] * inv1 + b0, 0.f),
                                       fmaxf(acc[3] * inv1 + b1, 0.f));
        }
        __syncthreads();                           // S3: half1+w reads done, sinv visible
        if (h < 7) {
            fill_half(h + 1, 128);
            CP_COMMIT();
        }
#pragma unroll
        for (int i = 0; i < 16; ++i)
            vacc[i] += 0.125f * w[i] * sinv[i];
        if (h < 7) {
            do_softmax(h + 1);
            CP_WAIT1();                            // ensure fill0(h+1) landed
            __syncthreads();                       // S4: half0(h+1)+w(h+1) visible
        }
    }

#pragma unroll
    for (int i = 0; i < 16; ++i)
        view[((size_t)b * 256 + i0 + i) * 256 + t] = vacc[i];

    float part = 0.f;
    float rs = g_rowsum[t >> 1];
#pragma unroll
    for (int pi = 0; pi < 8; ++pi) {
        float rm = fmaxf(vacc[2 * pi], vacc[2 * pi + 1]);
        rm = fmaxf(rm, __shfl_xor_sync(0xffffffffu, rm, 1));
        if (!(t & 1)) part += rm * rs;
    }
#pragma unroll
    for (int o = 16; o > 0; o >>= 1) part += __shfl_xor_sync(0xffffffffu, part, o);
    if (lane == 0) atomicAdd(&g_s[b], part);
}

// ---------------------------------------------------------------------------
// K4: dense4 = (view + I < sigmoid(s[b])) ? 1 : 0, float4-vectorized
// ---------------------------------------------------------------------------
__global__ void binarize_kernel(float4* __restrict__ view4) {
    int idx = blockIdx.x * 256 + threadIdx.x;   // 2097152 float4s
    int b = idx >> 14;
    int rem = idx & 16383;
    int i = rem >> 6, j0 = (rem & 63) << 2;
    float th = 1.f / (1.f + expf(-g_s[b]));
    float4 v = view4[idx];
    v.x += (j0 == i) ? 1.f : 0.f;
    v.y += (j0 + 1 == i) ? 1.f : 0.f;
    v.z += (j0 + 2 == i) ? 1.f : 0.f;
    v.w += (j0 + 3 == i) ? 1.f : 0.f;
    v.x = (v.x < th) ? 1.f : 0.f;
    v.y = (v.y < th) ? 1.f : 0.f;
    v.z = (v.z < th) ? 1.f : 0.f;
    v.w = (v.w < th) ? 1.f : 0.f;
    view4[idx] = v;
}

// ---------------------------------------------------------------------------
extern "C" void kernel_launch(void* const* d_in, const int* in_sizes, int n_in,
                              void* d_out, int out_size) {
    const float* X          = (const float*)d_in[0];
    const float* Aadj       = (const float*)d_in[1];
    const float* kernels    = (const float*)d_in[2];
    const float* biases     = (const float*)d_in[3];
    const float* attn_self  = (const float*)d_in[4];
    const float* attn_neigh = (const float*)d_in[5];
    const float* alpha      = (const float*)d_in[6];
    float* out  = (float*)d_out;            // [128,256,512]
    float* view = out + 16777216;           // dense4 region [128,256,256]

    cudaFuncSetAttribute(attn_kernel, cudaFuncAttributeMaxDynamicSharedMemorySize, AT_SIZE);
    cudaFuncSetAttribute(mma_gemm_kernel, cudaFuncAttributeMaxDynamicSharedMemorySize, GB_SMEM);

    prep_kernel<<<1024, 256>>>(kernels, alpha);
    mma_gemm_kernel<<<dim3(4, 256), 256, GB_SMEM>>>(X, attn_self, attn_neigh);
    attn_kernel<<<dim3(16, 128), 256, AT_SIZE>>>(Aadj, biases, out, view);
    binarize_kernel<<<8192, 256>>>((float4*)view);
}